// round 3
// baseline (speedup 1.0000x reference)
#include <cuda_runtime.h>
#include <cuda_bf16.h>
#include <cstdint>

// ---------------------------------------------------------------------------
// Problem constants
// ---------------------------------------------------------------------------
#define Bq   8
#define Nn_  1024
#define Cc   256
#define Hh   512
#define NLay 3
#define NHd  8
#define DH   64
#define ROWS (Bq * Nn_)          // 8192

// output layout (floats)
#define OFF_X  0
#define SZ_X   (ROWS * Hh)                 // 4,194,304
#define OFF_M  (OFF_X + SZ_X)
#define SZ_M   (ROWS)                      // 8,192
#define OFF_D  (OFF_M + SZ_M)
#define SZ_D   (ROWS * 5)                  // 40,960
#define OFF_P  (OFF_D + SZ_D)
#define SZ_P   (Bq * Nn_ * (Nn_ - 1))      // 8,380,416
#define OFF_G  (OFF_P + SZ_P)
#define SZ_G   (Bq * Hh)                   // 4,096

// ---------------------------------------------------------------------------
// Scratch (no allocation allowed -> __device__ globals)
// ---------------------------------------------------------------------------
__device__ float g_x   [ROWS * Hh];
__device__ float g_qkv [ROWS * 3 * Hh];
__device__ float g_atto[ROWS * Hh];
__device__ float g_att [ROWS * Hh];
__device__ float g_conv[ROWS * Hh];
__device__ float g_agg [ROWS * Hh];
__device__ float g_h1  [ROWS];
__device__ float g_h2  [ROWS];
__device__ float g_part[Bq * 8 * Hh];

// ---------------------------------------------------------------------------
// SGEMM: C[M,N] = A[M,K] @ op(B) + bias
//   TRANSB=true : B is [N,K] row-major (weight matrices, x @ W^T)
//   TRANSB=false: B is [K,N] row-major (adjacency @ conv)
// All of M,N divisible by 128 and K by 8 for our shapes -> no bounds checks.
// blockIdx.z = batch, with per-operand batch strides.
// ---------------------------------------------------------------------------
template<bool TRANSB, bool BIAS>
__global__ __launch_bounds__(256)
void sgemm_kernel(const float* __restrict__ A, const float* __restrict__ Bm,
                  const float* __restrict__ bias, float* __restrict__ C,
                  int M, int N, int K,
                  long long sA, long long sB, long long sC)
{
    constexpr int BM = 128, BN = 128, BK = 8, TM = 8, TN = 8;
    __shared__ float As[BK][BM];
    __shared__ float Bs[BK][BN];

    const int tid = threadIdx.x;
    const int nBase = blockIdx.x * BN;

    A  += (long long)blockIdx.z * sA + (long long)blockIdx.y * BM * K;
    Bm += (long long)blockIdx.z * sB;
    C  += (long long)blockIdx.z * sC + (long long)blockIdx.y * BM * N + nBase;

    const int aRow = tid >> 1;            // 0..127
    const int aCol = (tid & 1) * 4;       // 0 or 4
    const int bRow = tid >> 5;            // 0..7   (NN path)
    const int bCol = (tid & 31) * 4;      // 0..124 (NN path)

    const int ty = (tid >> 4) * TM;       // 0..120
    const int tx = (tid & 15) * TN;       // 0..120

    float acc[TM][TN];
#pragma unroll
    for (int i = 0; i < TM; i++)
#pragma unroll
        for (int j = 0; j < TN; j++) acc[i][j] = 0.f;

    for (int k0 = 0; k0 < K; k0 += BK) {
        float4 a4 = *reinterpret_cast<const float4*>(A + (long long)aRow * K + k0 + aCol);
        As[aCol + 0][aRow] = a4.x;
        As[aCol + 1][aRow] = a4.y;
        As[aCol + 2][aRow] = a4.z;
        As[aCol + 3][aRow] = a4.w;
        if (TRANSB) {
            float4 b4 = *reinterpret_cast<const float4*>(
                Bm + (long long)(nBase + aRow) * K + k0 + aCol);
            Bs[aCol + 0][aRow] = b4.x;
            Bs[aCol + 1][aRow] = b4.y;
            Bs[aCol + 2][aRow] = b4.z;
            Bs[aCol + 3][aRow] = b4.w;
        } else {
            float4 b4 = *reinterpret_cast<const float4*>(
                Bm + (long long)(k0 + bRow) * N + nBase + bCol);
            Bs[bRow][bCol + 0] = b4.x;
            Bs[bRow][bCol + 1] = b4.y;
            Bs[bRow][bCol + 2] = b4.z;
            Bs[bRow][bCol + 3] = b4.w;
        }
        __syncthreads();

#pragma unroll
        for (int k = 0; k < BK; k++) {
            float ra[TM], rb[TN];
#pragma unroll
            for (int i = 0; i < TM; i++) ra[i] = As[k][ty + i];
#pragma unroll
            for (int j = 0; j < TN; j++) rb[j] = Bs[k][tx + j];
#pragma unroll
            for (int i = 0; i < TM; i++)
#pragma unroll
                for (int j = 0; j < TN; j++)
                    acc[i][j] += ra[i] * rb[j];
        }
        __syncthreads();
    }

#pragma unroll
    for (int i = 0; i < TM; i++) {
#pragma unroll
        for (int j = 0; j < TN; j += 4) {
            float4 r;
            r.x = acc[i][j + 0];
            r.y = acc[i][j + 1];
            r.z = acc[i][j + 2];
            r.w = acc[i][j + 3];
            if (BIAS) {
                r.x += bias[nBase + tx + j + 0];
                r.y += bias[nBase + tx + j + 1];
                r.z += bias[nBase + tx + j + 2];
                r.w += bias[nBase + tx + j + 3];
            }
            *reinterpret_cast<float4*>(C + (long long)(ty + i) * N + tx + j) = r;
        }
    }
}

// ---------------------------------------------------------------------------
// Attention: torch MHA with batch_first=False => attention over the B=8 axis.
// For each (n, head): scores[8][8] = q_i . k_j / 8 ; softmax over j ; o = a @ v
// One block of 64 threads per (n, head).
// qkv: [B, N, 3H]  out: [B, N, H]
// ---------------------------------------------------------------------------
__global__ __launch_bounds__(64)
void attention_kernel(const float* __restrict__ qkv, float* __restrict__ out)
{
    const int nh = blockIdx.x;           // 0..N*NH-1
    const int n  = nh >> 3;              // /NH
    const int h  = nh & 7;
    const int t  = threadIdx.x;          // 0..63

    __shared__ float q[8][64];
    __shared__ float k[8][65];
    __shared__ float v[8][65];
    __shared__ float a[8][9];

    const int row3H = 3 * Hh;
    const float* base = qkv + (long long)n * row3H + h * DH;
#pragma unroll
    for (int i = 0; i < Bq; i++) {
        const float* p = base + (long long)i * Nn_ * row3H;
        q[i][t] = p[t];
        k[i][t] = p[Hh + t];
        v[i][t] = p[2 * Hh + t];
    }
    __syncthreads();

    {
        const int si = t >> 3, sj = t & 7;
        float s = 0.f;
#pragma unroll
        for (int d = 0; d < DH; d++) s += q[si][d] * k[sj][d];
        a[si][sj] = s * 0.125f;          // 1/sqrt(64)
    }
    __syncthreads();

    if (t < Bq) {
        float m = -1e30f;
#pragma unroll
        for (int j = 0; j < Bq; j++) m = fmaxf(m, a[t][j]);
        float sum = 0.f;
#pragma unroll
        for (int j = 0; j < Bq; j++) { float e = expf(a[t][j] - m); a[t][j] = e; sum += e; }
        float inv = 1.f / sum;
#pragma unroll
        for (int j = 0; j < Bq; j++) a[t][j] *= inv;
    }
    __syncthreads();

    float* ob = out + (long long)n * Hh + h * DH + t;
#pragma unroll
    for (int i = 0; i < Bq; i++) {
        float o = 0.f;
#pragma unroll
        for (int j = 0; j < Bq; j++) o += a[i][j] * v[j][t];
        ob[(long long)i * Nn_ * Hh] = o;
    }
}

// ---------------------------------------------------------------------------
// out = layernorm(x + agg) over the last dim (H=512), eps=1e-5, no affine.
// One block (256 threads) per row; safe in-place (reads precede writes).
// ---------------------------------------------------------------------------
__global__ __launch_bounds__(256)
void add_ln_kernel(const float* __restrict__ x, const float* __restrict__ agg,
                   float* __restrict__ out)
{
    const int row = blockIdx.x;
    const int t   = threadIdx.x;
    const float* xr = x   + (long long)row * Hh;
    const float* ar = agg + (long long)row * Hh;

    float v0 = xr[t]       + ar[t];
    float v1 = xr[t + 256] + ar[t + 256];
    float s  = v0 + v1;
    float ss = v0 * v0 + v1 * v1;

#pragma unroll
    for (int o = 16; o; o >>= 1) {
        s  += __shfl_xor_sync(0xffffffffu, s,  o);
        ss += __shfl_xor_sync(0xffffffffu, ss, o);
    }
    __shared__ float sb[8], qb[8];
    if ((t & 31) == 0) { sb[t >> 5] = s; qb[t >> 5] = ss; }
    __syncthreads();
    if (t < 32) {
        float a2 = (t < 8) ? sb[t] : 0.f;
        float b2 = (t < 8) ? qb[t] : 0.f;
#pragma unroll
        for (int o = 4; o; o >>= 1) {
            a2 += __shfl_xor_sync(0xffffffffu, a2, o);
            b2 += __shfl_xor_sync(0xffffffffu, b2, o);
        }
        if (t == 0) { sb[0] = a2; qb[0] = b2; }
    }
    __syncthreads();

    const float mean = sb[0] * (1.f / Hh);
    const float var  = qb[0] * (1.f / Hh) - mean * mean;
    const float inv  = rsqrtf(var + 1e-5f);
    float* orow = out + (long long)row * Hh;
    orow[t]       = (v0 - mean) * inv;
    orow[t + 256] = (v1 - mean) * inv;
}

// ---------------------------------------------------------------------------
// Heads: one pass over each x row computes 8 dot products:
//   mastery (W_cls), diff[5] (W_diff), h1 = x.W_pre[:512], h2 = x.W_pre[512:]
// ---------------------------------------------------------------------------
__global__ __launch_bounds__(256)
void heads_kernel(const float* __restrict__ x,
                  const float* __restrict__ Wcls, const float* __restrict__ bcls,
                  const float* __restrict__ Wdiff, const float* __restrict__ bdiff,
                  const float* __restrict__ Wpre,
                  float* __restrict__ mastery, float* __restrict__ diff,
                  float* __restrict__ h1, float* __restrict__ h2)
{
    const int row = blockIdx.x;
    const int t   = threadIdx.x;
    const float* xr = x + (long long)row * Hh;

    float acc[8] = {0.f, 0.f, 0.f, 0.f, 0.f, 0.f, 0.f, 0.f};
    for (int c = t; c < Hh; c += 256) {
        const float xv = xr[c];
        acc[0] += xv * Wcls[c];
#pragma unroll
        for (int kk = 0; kk < 5; kk++) acc[1 + kk] += xv * Wdiff[kk * Hh + c];
        acc[6] += xv * Wpre[c];
        acc[7] += xv * Wpre[Hh + c];
    }

    __shared__ float r[8][8];
#pragma unroll
    for (int kk = 0; kk < 8; kk++) {
        float v = acc[kk];
#pragma unroll
        for (int o = 16; o; o >>= 1) v += __shfl_xor_sync(0xffffffffu, v, o);
        if ((t & 31) == 0) r[kk][t >> 5] = v;
    }
    __syncthreads();
    if (t < 8) {
        float s = 0.f;
#pragma unroll
        for (int w = 0; w < 8; w++) s += r[t][w];
        if      (t == 0) mastery[row] = s + bcls[0];
        else if (t < 6)  diff[(long long)row * 5 + (t - 1)] = s + bdiff[t - 1];
        else if (t == 6) h1[row] = s;
        else             h2[row] = s;
    }
}

// ---------------------------------------------------------------------------
// prereq: pair(i,j) = h1[b,i] + h2[b,j] + b_pre, for all i != j (row-major,
// diagonal removed): out index = b*N*(N-1) + i*(N-1) + j - (j>i)
// ---------------------------------------------------------------------------
__global__ __launch_bounds__(256)
void prereq_kernel(const float* __restrict__ h1, const float* __restrict__ h2,
                   const float* __restrict__ bpre, float* __restrict__ out)
{
    const long long idx = (long long)blockIdx.x * blockDim.x + threadIdx.x;
    const int j = (int)(idx & (Nn_ - 1));
    const int i = (int)((idx >> 10) & (Nn_ - 1));
    const int b = (int)(idx >> 20);
    if (b >= Bq || i == j) return;
    const long long o = (long long)b * Nn_ * (Nn_ - 1) + (long long)i * (Nn_ - 1) + j - (j > i);
    out[o] = h1[b * Nn_ + i] + h2[b * Nn_ + j] + bpre[0];
}

// ---------------------------------------------------------------------------
// Pooling: partial sums over n (8 groups of 128 rows), then mean + W_pool GEMV.
// ---------------------------------------------------------------------------
__global__ __launch_bounds__(512)
void pool_partial_kernel(const float* __restrict__ x, float* __restrict__ part)
{
    const int b = blockIdx.x, g = blockIdx.y, t = threadIdx.x;
    float s = 0.f;
    const float* base = x + ((long long)b * Nn_ + g * 128) * Hh + t;
    for (int n = 0; n < 128; n++) s += base[(long long)n * Hh];
    part[((long long)b * 8 + g) * Hh + t] = s;
}

__global__ __launch_bounds__(512)
void graph_kernel(const float* __restrict__ part, const float* __restrict__ Wp,
                  const float* __restrict__ bp, float* __restrict__ out)
{
    const int b = blockIdx.x, t = threadIdx.x;
    __shared__ float xm[Hh];
    float s = 0.f;
#pragma unroll
    for (int g = 0; g < 8; g++) s += part[((long long)b * 8 + g) * Hh + t];
    xm[t] = s * (1.f / Nn_);
    __syncthreads();
    float acc = 0.f;
    const float* wr = Wp + (long long)t * Hh;
    for (int c = 0; c < Hh; c++) acc += xm[c] * wr[c];
    out[(long long)b * Hh + t] = acc + bp[t];
}

// ---------------------------------------------------------------------------
// Launcher
// ---------------------------------------------------------------------------
extern "C" void kernel_launch(void* const* d_in, const int* in_sizes, int n_in,
                              void* d_out, int out_size)
{
    const float* CF    = (const float*)d_in[0];
    const float* ADJ   = (const float*)d_in[1];
    // d_in[2] = edge_types (unused), d_in[3] = concept_mask (unused)
    const float* Wemb  = (const float*)d_in[4];
    const float* bemb  = (const float*)d_in[5];
    const float* Win   = (const float*)d_in[6];
    const float* bin   = (const float*)d_in[7];
    const float* Wout  = (const float*)d_in[8];
    const float* bout  = (const float*)d_in[9];
    const float* Wconv = (const float*)d_in[10];
    const float* bconv = (const float*)d_in[11];
    const float* Wcls  = (const float*)d_in[12];
    const float* bcls  = (const float*)d_in[13];
    const float* Wdiff = (const float*)d_in[14];
    const float* bdiff = (const float*)d_in[15];
    const float* Wpre  = (const float*)d_in[16];
    const float* bpre  = (const float*)d_in[17];
    const float* Wpool = (const float*)d_in[18];
    const float* bpool = (const float*)d_in[19];

    float *x, *qkv, *atto, *att, *conv, *agg, *h1, *h2, *part;
    cudaGetSymbolAddress((void**)&x,    g_x);
    cudaGetSymbolAddress((void**)&qkv,  g_qkv);
    cudaGetSymbolAddress((void**)&atto, g_atto);
    cudaGetSymbolAddress((void**)&att,  g_att);
    cudaGetSymbolAddress((void**)&conv, g_conv);
    cudaGetSymbolAddress((void**)&agg,  g_agg);
    cudaGetSymbolAddress((void**)&h1,   g_h1);
    cudaGetSymbolAddress((void**)&h2,   g_h2);
    cudaGetSymbolAddress((void**)&part, g_part);

    float* out   = (float*)d_out;
    float* out_x = out + OFF_X;
    float* out_m = out + OFF_M;
    float* out_d = out + OFF_D;
    float* out_p = out + OFF_P;
    float* out_g = out + OFF_G;

    // x = concept_features @ W_emb^T + b_emb   (8192 x 256 -> 8192 x 512)
    sgemm_kernel<true, true><<<dim3(Hh / 128, ROWS / 128, 1), 256>>>(
        CF, Wemb, bemb, x, ROWS, Hh, Cc, 0, 0, 0);

    for (int l = 0; l < NLay; l++) {
        // qkv = x @ W_in[l]^T + b_in[l]   (8192 x 512 -> 8192 x 1536)
        sgemm_kernel<true, true><<<dim3(3 * Hh / 128, ROWS / 128, 1), 256>>>(
            x, Win + (long long)l * 3 * Hh * Hh, bin + l * 3 * Hh, qkv,
            ROWS, 3 * Hh, Hh, 0, 0, 0);

        // attention over B axis
        attention_kernel<<<Nn_ * NHd, 64>>>(qkv, atto);

        // att = atto @ W_out[l]^T + b_out[l]
        sgemm_kernel<true, true><<<dim3(Hh / 128, ROWS / 128, 1), 256>>>(
            atto, Wout + (long long)l * Hh * Hh, bout + l * Hh, att,
            ROWS, Hh, Hh, 0, 0, 0);

        // conv = att @ W_conv[l]^T + b_conv[l]
        sgemm_kernel<true, true><<<dim3(Hh / 128, ROWS / 128, 1), 256>>>(
            att, Wconv + (long long)l * Hh * Hh, bconv + l * Hh, conv,
            ROWS, Hh, Hh, 0, 0, 0);

        // agg[b] = adj[b] @ conv[b]   (batched NN GEMM, 8 x [1024x1024 @ 1024x512])
        sgemm_kernel<false, false><<<dim3(Hh / 128, Nn_ / 128, Bq), 256>>>(
            ADJ, conv, nullptr, agg, Nn_, Hh, Nn_,
            (long long)Nn_ * Nn_, (long long)Nn_ * Hh, (long long)Nn_ * Hh);

        // x = layernorm(x + agg); last layer writes straight into d_out
        add_ln_kernel<<<ROWS, 256>>>(x, agg, (l == NLay - 1) ? out_x : x);
    }

    // mastery / diff / h1 / h2 in one pass
    heads_kernel<<<ROWS, 256>>>(out_x, Wcls, bcls, Wdiff, bdiff, Wpre,
                                out_m, out_d, h1, h2);

    // prereq pairwise expansion (8.38M outputs)
    prereq_kernel<<<(Bq * Nn_ * Nn_) / 256, 256>>>(h1, h2, bpre, out_p);

    // graph pooling
    pool_partial_kernel<<<dim3(Bq, 8), 512>>>(out_x, part);
    graph_kernel<<<Bq, 512>>>(part, Wpool, bpool, out_g);
}

// round 4
// speedup vs baseline: 1.0002x; 1.0002x over previous
#include <cuda_runtime.h>
#include <cuda_bf16.h>
#include <cstdint>

// ---------------------------------------------------------------------------
// Problem constants
// ---------------------------------------------------------------------------
#define Bq   8
#define Nn_  1024
#define Cc   256
#define Hh   512
#define NLay 3
#define NHd  8
#define DH   64
#define ROWS (Bq * Nn_)          // 8192

// output layout (floats)
#define OFF_X  0
#define SZ_X   (ROWS * Hh)                 // 4,194,304
#define OFF_M  (OFF_X + SZ_X)
#define SZ_M   (ROWS)                      // 8,192
#define OFF_D  (OFF_M + SZ_M)
#define SZ_D   (ROWS * 5)                  // 40,960
#define OFF_P  (OFF_D + SZ_D)
#define SZ_P   (Bq * Nn_ * (Nn_ - 1))      // 8,380,416
#define OFF_G  (OFF_P + SZ_P)
#define SZ_G   (Bq * Hh)                   // 4,096

// ---------------------------------------------------------------------------
// Scratch (no allocation allowed -> __device__ globals)
// ---------------------------------------------------------------------------
__device__ float g_x   [ROWS * Hh];
__device__ float g_qkv [ROWS * 3 * Hh];
__device__ float g_atto[ROWS * Hh];
__device__ float g_att [ROWS * Hh];
__device__ float g_conv[ROWS * Hh];
__device__ float g_agg [ROWS * Hh];
__device__ float g_h1  [ROWS];
__device__ float g_h2  [ROWS];
__device__ float g_part[Bq * 8 * Hh];

// ---------------------------------------------------------------------------
// SGEMM: C[M,N] = A[M,K] @ op(B) + bias
//   TRANSB=true : B is [N,K] row-major (weight matrices, x @ W^T)
//   TRANSB=false: B is [K,N] row-major (adjacency @ conv)
// All of M,N divisible by 128 and K by 8 for our shapes -> no bounds checks.
// blockIdx.z = batch, with per-operand batch strides.
// ---------------------------------------------------------------------------
template<bool TRANSB, bool BIAS>
__global__ __launch_bounds__(256)
void sgemm_kernel(const float* __restrict__ A, const float* __restrict__ Bm,
                  const float* __restrict__ bias, float* __restrict__ C,
                  int M, int N, int K,
                  long long sA, long long sB, long long sC)
{
    constexpr int BM = 128, BN = 128, BK = 8, TM = 8, TN = 8;
    __shared__ float As[BK][BM];
    __shared__ float Bs[BK][BN];

    const int tid = threadIdx.x;
    const int nBase = blockIdx.x * BN;

    A  += (long long)blockIdx.z * sA + (long long)blockIdx.y * BM * K;
    Bm += (long long)blockIdx.z * sB;
    C  += (long long)blockIdx.z * sC + (long long)blockIdx.y * BM * N + nBase;

    const int aRow = tid >> 1;            // 0..127
    const int aCol = (tid & 1) * 4;       // 0 or 4
    const int bRow = tid >> 5;            // 0..7   (NN path)
    const int bCol = (tid & 31) * 4;      // 0..124 (NN path)

    const int ty = (tid >> 4) * TM;       // 0..120
    const int tx = (tid & 15) * TN;       // 0..120

    float acc[TM][TN];
#pragma unroll
    for (int i = 0; i < TM; i++)
#pragma unroll
        for (int j = 0; j < TN; j++) acc[i][j] = 0.f;

    for (int k0 = 0; k0 < K; k0 += BK) {
        float4 a4 = *reinterpret_cast<const float4*>(A + (long long)aRow * K + k0 + aCol);
        As[aCol + 0][aRow] = a4.x;
        As[aCol + 1][aRow] = a4.y;
        As[aCol + 2][aRow] = a4.z;
        As[aCol + 3][aRow] = a4.w;
        if (TRANSB) {
            float4 b4 = *reinterpret_cast<const float4*>(
                Bm + (long long)(nBase + aRow) * K + k0 + aCol);
            Bs[aCol + 0][aRow] = b4.x;
            Bs[aCol + 1][aRow] = b4.y;
            Bs[aCol + 2][aRow] = b4.z;
            Bs[aCol + 3][aRow] = b4.w;
        } else {
            float4 b4 = *reinterpret_cast<const float4*>(
                Bm + (long long)(k0 + bRow) * N + nBase + bCol);
            Bs[bRow][bCol + 0] = b4.x;
            Bs[bRow][bCol + 1] = b4.y;
            Bs[bRow][bCol + 2] = b4.z;
            Bs[bRow][bCol + 3] = b4.w;
        }
        __syncthreads();

#pragma unroll
        for (int k = 0; k < BK; k++) {
            float ra[TM], rb[TN];
#pragma unroll
            for (int i = 0; i < TM; i++) ra[i] = As[k][ty + i];
#pragma unroll
            for (int j = 0; j < TN; j++) rb[j] = Bs[k][tx + j];
#pragma unroll
            for (int i = 0; i < TM; i++)
#pragma unroll
                for (int j = 0; j < TN; j++)
                    acc[i][j] += ra[i] * rb[j];
        }
        __syncthreads();
    }

#pragma unroll
    for (int i = 0; i < TM; i++) {
#pragma unroll
        for (int j = 0; j < TN; j += 4) {
            float4 r;
            r.x = acc[i][j + 0];
            r.y = acc[i][j + 1];
            r.z = acc[i][j + 2];
            r.w = acc[i][j + 3];
            if (BIAS) {
                r.x += bias[nBase + tx + j + 0];
                r.y += bias[nBase + tx + j + 1];
                r.z += bias[nBase + tx + j + 2];
                r.w += bias[nBase + tx + j + 3];
            }
            *reinterpret_cast<float4*>(C + (long long)(ty + i) * N + tx + j) = r;
        }
    }
}

// ---------------------------------------------------------------------------
// Attention: torch MHA with batch_first=False => attention over the B=8 axis.
// For each (n, head): scores[8][8] = q_i . k_j / 8 ; softmax over j ; o = a @ v
// One block of 64 threads per (n, head).
// qkv: [B, N, 3H]  out: [B, N, H]
// ---------------------------------------------------------------------------
__global__ __launch_bounds__(64)
void attention_kernel(const float* __restrict__ qkv, float* __restrict__ out)
{
    const int nh = blockIdx.x;           // 0..N*NH-1
    const int n  = nh >> 3;              // /NH
    const int h  = nh & 7;
    const int t  = threadIdx.x;          // 0..63

    __shared__ float q[8][64];
    __shared__ float k[8][65];
    __shared__ float v[8][65];
    __shared__ float a[8][9];

    const int row3H = 3 * Hh;
    const float* base = qkv + (long long)n * row3H + h * DH;
#pragma unroll
    for (int i = 0; i < Bq; i++) {
        const float* p = base + (long long)i * Nn_ * row3H;
        q[i][t] = p[t];
        k[i][t] = p[Hh + t];
        v[i][t] = p[2 * Hh + t];
    }
    __syncthreads();

    {
        const int si = t >> 3, sj = t & 7;
        float s = 0.f;
#pragma unroll
        for (int d = 0; d < DH; d++) s += q[si][d] * k[sj][d];
        a[si][sj] = s * 0.125f;          // 1/sqrt(64)
    }
    __syncthreads();

    if (t < Bq) {
        float m = -1e30f;
#pragma unroll
        for (int j = 0; j < Bq; j++) m = fmaxf(m, a[t][j]);
        float sum = 0.f;
#pragma unroll
        for (int j = 0; j < Bq; j++) { float e = expf(a[t][j] - m); a[t][j] = e; sum += e; }
        float inv = 1.f / sum;
#pragma unroll
        for (int j = 0; j < Bq; j++) a[t][j] *= inv;
    }
    __syncthreads();

    float* ob = out + (long long)n * Hh + h * DH + t;
#pragma unroll
    for (int i = 0; i < Bq; i++) {
        float o = 0.f;
#pragma unroll
        for (int j = 0; j < Bq; j++) o += a[i][j] * v[j][t];
        ob[(long long)i * Nn_ * Hh] = o;
    }
}

// ---------------------------------------------------------------------------
// out = layernorm(x + agg) over the last dim (H=512), eps=1e-5, no affine.
// One block (256 threads) per row; safe in-place (reads precede writes).
// ---------------------------------------------------------------------------
__global__ __launch_bounds__(256)
void add_ln_kernel(const float* __restrict__ x, const float* __restrict__ agg,
                   float* __restrict__ out)
{
    const int row = blockIdx.x;
    const int t   = threadIdx.x;
    const float* xr = x   + (long long)row * Hh;
    const float* ar = agg + (long long)row * Hh;

    float v0 = xr[t]       + ar[t];
    float v1 = xr[t + 256] + ar[t + 256];
    float s  = v0 + v1;
    float ss = v0 * v0 + v1 * v1;

#pragma unroll
    for (int o = 16; o; o >>= 1) {
        s  += __shfl_xor_sync(0xffffffffu, s,  o);
        ss += __shfl_xor_sync(0xffffffffu, ss, o);
    }
    __shared__ float sb[8], qb[8];
    if ((t & 31) == 0) { sb[t >> 5] = s; qb[t >> 5] = ss; }
    __syncthreads();
    if (t < 32) {
        float a2 = (t < 8) ? sb[t] : 0.f;
        float b2 = (t < 8) ? qb[t] : 0.f;
#pragma unroll
        for (int o = 4; o; o >>= 1) {
            a2 += __shfl_xor_sync(0xffffffffu, a2, o);
            b2 += __shfl_xor_sync(0xffffffffu, b2, o);
        }
        if (t == 0) { sb[0] = a2; qb[0] = b2; }
    }
    __syncthreads();

    const float mean = sb[0] * (1.f / Hh);
    const float var  = qb[0] * (1.f / Hh) - mean * mean;
    const float inv  = rsqrtf(var + 1e-5f);
    float* orow = out + (long long)row * Hh;
    orow[t]       = (v0 - mean) * inv;
    orow[t + 256] = (v1 - mean) * inv;
}

// ---------------------------------------------------------------------------
// Heads: one pass over each x row computes 8 dot products:
//   mastery (W_cls), diff[5] (W_diff), h1 = x.W_pre[:512], h2 = x.W_pre[512:]
// ---------------------------------------------------------------------------
__global__ __launch_bounds__(256)
void heads_kernel(const float* __restrict__ x,
                  const float* __restrict__ Wcls, const float* __restrict__ bcls,
                  const float* __restrict__ Wdiff, const float* __restrict__ bdiff,
                  const float* __restrict__ Wpre,
                  float* __restrict__ mastery, float* __restrict__ diff,
                  float* __restrict__ h1, float* __restrict__ h2)
{
    const int row = blockIdx.x;
    const int t   = threadIdx.x;
    const float* xr = x + (long long)row * Hh;

    float acc[8] = {0.f, 0.f, 0.f, 0.f, 0.f, 0.f, 0.f, 0.f};
    for (int c = t; c < Hh; c += 256) {
        const float xv = xr[c];
        acc[0] += xv * Wcls[c];
#pragma unroll
        for (int kk = 0; kk < 5; kk++) acc[1 + kk] += xv * Wdiff[kk * Hh + c];
        acc[6] += xv * Wpre[c];
        acc[7] += xv * Wpre[Hh + c];
    }

    __shared__ float r[8][8];
#pragma unroll
    for (int kk = 0; kk < 8; kk++) {
        float v = acc[kk];
#pragma unroll
        for (int o = 16; o; o >>= 1) v += __shfl_xor_sync(0xffffffffu, v, o);
        if ((t & 31) == 0) r[kk][t >> 5] = v;
    }
    __syncthreads();
    if (t < 8) {
        float s = 0.f;
#pragma unroll
        for (int w = 0; w < 8; w++) s += r[t][w];
        if      (t == 0) mastery[row] = s + bcls[0];
        else if (t < 6)  diff[(long long)row * 5 + (t - 1)] = s + bdiff[t - 1];
        else if (t == 6) h1[row] = s;
        else             h2[row] = s;
    }
}

// ---------------------------------------------------------------------------
// prereq: pair(i,j) = h1[b,i] + h2[b,j] + b_pre, for all i != j (row-major,
// diagonal removed): out index = b*N*(N-1) + i*(N-1) + j - (j>i)
// ---------------------------------------------------------------------------
__global__ __launch_bounds__(256)
void prereq_kernel(const float* __restrict__ h1, const float* __restrict__ h2,
                   const float* __restrict__ bpre, float* __restrict__ out)
{
    const long long idx = (long long)blockIdx.x * blockDim.x + threadIdx.x;
    const int j = (int)(idx & (Nn_ - 1));
    const int i = (int)((idx >> 10) & (Nn_ - 1));
    const int b = (int)(idx >> 20);
    if (b >= Bq || i == j) return;
    const long long o = (long long)b * Nn_ * (Nn_ - 1) + (long long)i * (Nn_ - 1) + j - (j > i);
    out[o] = h1[b * Nn_ + i] + h2[b * Nn_ + j] + bpre[0];
}

// ---------------------------------------------------------------------------
// Pooling: partial sums over n (8 groups of 128 rows), then mean + W_pool GEMV.
// ---------------------------------------------------------------------------
__global__ __launch_bounds__(512)
void pool_partial_kernel(const float* __restrict__ x, float* __restrict__ part)
{
    const int b = blockIdx.x, g = blockIdx.y, t = threadIdx.x;
    float s = 0.f;
    const float* base = x + ((long long)b * Nn_ + g * 128) * Hh + t;
    for (int n = 0; n < 128; n++) s += base[(long long)n * Hh];
    part[((long long)b * 8 + g) * Hh + t] = s;
}

__global__ __launch_bounds__(512)
void graph_kernel(const float* __restrict__ part, const float* __restrict__ Wp,
                  const float* __restrict__ bp, float* __restrict__ out)
{
    const int b = blockIdx.x, t = threadIdx.x;
    __shared__ float xm[Hh];
    float s = 0.f;
#pragma unroll
    for (int g = 0; g < 8; g++) s += part[((long long)b * 8 + g) * Hh + t];
    xm[t] = s * (1.f / Nn_);
    __syncthreads();
    float acc = 0.f;
    const float* wr = Wp + (long long)t * Hh;
    for (int c = 0; c < Hh; c++) acc += xm[c] * wr[c];
    out[(long long)b * Hh + t] = acc + bp[t];
}

// ---------------------------------------------------------------------------
// Launcher
// ---------------------------------------------------------------------------
extern "C" void kernel_launch(void* const* d_in, const int* in_sizes, int n_in,
                              void* d_out, int out_size)
{
    const float* CF    = (const float*)d_in[0];
    const float* ADJ   = (const float*)d_in[1];
    // d_in[2] = edge_types (unused), d_in[3] = concept_mask (unused)
    const float* Wemb  = (const float*)d_in[4];
    const float* bemb  = (const float*)d_in[5];
    const float* Win   = (const float*)d_in[6];
    const float* bin   = (const float*)d_in[7];
    const float* Wout  = (const float*)d_in[8];
    const float* bout  = (const float*)d_in[9];
    const float* Wconv = (const float*)d_in[10];
    const float* bconv = (const float*)d_in[11];
    const float* Wcls  = (const float*)d_in[12];
    const float* bcls  = (const float*)d_in[13];
    const float* Wdiff = (const float*)d_in[14];
    const float* bdiff = (const float*)d_in[15];
    const float* Wpre  = (const float*)d_in[16];
    const float* bpre  = (const float*)d_in[17];
    const float* Wpool = (const float*)d_in[18];
    const float* bpool = (const float*)d_in[19];

    float *x, *qkv, *atto, *att, *conv, *agg, *h1, *h2, *part;
    cudaGetSymbolAddress((void**)&x,    g_x);
    cudaGetSymbolAddress((void**)&qkv,  g_qkv);
    cudaGetSymbolAddress((void**)&atto, g_atto);
    cudaGetSymbolAddress((void**)&att,  g_att);
    cudaGetSymbolAddress((void**)&conv, g_conv);
    cudaGetSymbolAddress((void**)&agg,  g_agg);
    cudaGetSymbolAddress((void**)&h1,   g_h1);
    cudaGetSymbolAddress((void**)&h2,   g_h2);
    cudaGetSymbolAddress((void**)&part, g_part);

    float* out   = (float*)d_out;
    float* out_x = out + OFF_X;
    float* out_m = out + OFF_M;
    float* out_d = out + OFF_D;
    float* out_p = out + OFF_P;
    float* out_g = out + OFF_G;

    // x = concept_features @ W_emb^T + b_emb   (8192 x 256 -> 8192 x 512)
    sgemm_kernel<true, true><<<dim3(Hh / 128, ROWS / 128, 1), 256>>>(
        CF, Wemb, bemb, x, ROWS, Hh, Cc, 0, 0, 0);

    for (int l = 0; l < NLay; l++) {
        // qkv = x @ W_in[l]^T + b_in[l]   (8192 x 512 -> 8192 x 1536)
        sgemm_kernel<true, true><<<dim3(3 * Hh / 128, ROWS / 128, 1), 256>>>(
            x, Win + (long long)l * 3 * Hh * Hh, bin + l * 3 * Hh, qkv,
            ROWS, 3 * Hh, Hh, 0, 0, 0);

        // attention over B axis
        attention_kernel<<<Nn_ * NHd, 64>>>(qkv, atto);

        // att = atto @ W_out[l]^T + b_out[l]
        sgemm_kernel<true, true><<<dim3(Hh / 128, ROWS / 128, 1), 256>>>(
            atto, Wout + (long long)l * Hh * Hh, bout + l * Hh, att,
            ROWS, Hh, Hh, 0, 0, 0);

        // conv = att @ W_conv[l]^T + b_conv[l]
        sgemm_kernel<true, true><<<dim3(Hh / 128, ROWS / 128, 1), 256>>>(
            att, Wconv + (long long)l * Hh * Hh, bconv + l * Hh, conv,
            ROWS, Hh, Hh, 0, 0, 0);

        // agg[b] = adj[b] @ conv[b]   (batched NN GEMM, 8 x [1024x1024 @ 1024x512])
        sgemm_kernel<false, false><<<dim3(Hh / 128, Nn_ / 128, Bq), 256>>>(
            ADJ, conv, nullptr, agg, Nn_, Hh, Nn_,
            (long long)Nn_ * Nn_, (long long)Nn_ * Hh, (long long)Nn_ * Hh);

        // x = layernorm(x + agg); last layer writes straight into d_out
        add_ln_kernel<<<ROWS, 256>>>(x, agg, (l == NLay - 1) ? out_x : x);
    }

    // mastery / diff / h1 / h2 in one pass
    heads_kernel<<<ROWS, 256>>>(out_x, Wcls, bcls, Wdiff, bdiff, Wpre,
                                out_m, out_d, h1, h2);

    // prereq pairwise expansion (8.38M outputs)
    prereq_kernel<<<(Bq * Nn_ * Nn_) / 256, 256>>>(h1, h2, bpre, out_p);

    // graph pooling
    pool_partial_kernel<<<dim3(Bq, 8), 512>>>(out_x, part);
    graph_kernel<<<Bq, 512>>>(part, Wpool, bpool, out_g);
}

// round 9
// speedup vs baseline: 2.3032x; 2.3027x over previous
#include <cuda_runtime.h>
#include <cuda_bf16.h>
#include <cstdint>
#include <cstddef>

// ---------------------------------------------------------------------------
// Problem constants
// ---------------------------------------------------------------------------
#define Bq   8
#define Nn_  1024
#define Cc   256
#define Hh   512
#define NLay 3
#define NHd  8
#define DH   64
#define ROWS (Bq * Nn_)          // 8192

// output layout (floats)
#define OFF_X  0
#define SZ_X   (ROWS * Hh)
#define OFF_M  (OFF_X + SZ_X)
#define SZ_M   (ROWS)
#define OFF_D  (OFF_M + SZ_M)
#define SZ_D   (ROWS * 5)
#define OFF_P  (OFF_D + SZ_D)
#define SZ_P   (Bq * Nn_ * (Nn_ - 1))
#define OFF_G  (OFF_P + SZ_P)
#define SZ_G   (Bq * Hh)

// ---------------------------------------------------------------------------
// Helpers (all plain sm_80/sm_90 PTX -- compiles under compute_103 virtual arch)
// ---------------------------------------------------------------------------
__device__ __forceinline__ uint32_t smem_u32(const void* p) {
    uint32_t a;
    asm("{ .reg .u64 t; cvta.to.shared.u64 t, %1; cvt.u32.u64 %0, t; }"
        : "=r"(a) : "l"(p));
    return a;
}

#define CP_ASYNC_16(dst, src) \
    asm volatile("cp.async.cg.shared.global [%0], [%1], 16;" \
                 :: "r"(dst), "l"(src) : "memory")
#define CP_COMMIT() asm volatile("cp.async.commit_group;" ::: "memory")

#define LDSM4(r, addr) \
    asm volatile("ldmatrix.sync.aligned.m8n8.x4.shared.b16 {%0,%1,%2,%3}, [%4];" \
        : "=r"((r)[0]), "=r"((r)[1]), "=r"((r)[2]), "=r"((r)[3]) : "r"(addr))

#define MMA_BF16(d, a, b0, b1) \
    asm volatile("mma.sync.aligned.m16n8k16.row.col.f32.bf16.bf16.f32 " \
        "{%0,%1,%2,%3}, {%4,%5,%6,%7}, {%8,%9}, {%0,%1,%2,%3};" \
        : "+f"((d)[0]), "+f"((d)[1]), "+f"((d)[2]), "+f"((d)[3]) \
        : "r"((a)[0]), "r"((a)[1]), "r"((a)[2]), "r"((a)[3]), "r"(b0), "r"(b1))

__device__ __forceinline__ void split_bf16(float a, unsigned short& hb, unsigned short& lb) {
    __nv_bfloat16 h = __float2bfloat16(a);
    float l = a - __bfloat162float(h);
    __nv_bfloat16 lo = __float2bfloat16(l);
    hb = *reinterpret_cast<unsigned short*>(&h);
    lb = *reinterpret_cast<unsigned short*>(&lo);
}

// swizzled byte offset inside a 128x64-bf16 tile (128 B/row, SW128 pattern)
__device__ __forceinline__ int swz(int r, int k) {
    return r * 128 + ((((k >> 3) ^ (r & 7)) << 4)) + (k & 7) * 2;
}

// ---------------------------------------------------------------------------
// Scratch (__device__ globals). Tiled hi/lo format: matrix [R,K] stored as
// (R/128)*(K/64) tiles of 32KB: 16KB hi (swizzled) + 16KB lo.
// tile index = rowTile*(K/64) + kChunk.
// ---------------------------------------------------------------------------
__device__ __align__(128) float g_x   [ROWS * Hh];
__device__ __align__(128) float g_qkv [ROWS * 3 * Hh];
__device__ __align__(128) float g_agg [ROWS * Hh];
__device__ __align__(128) float g_h1  [ROWS];
__device__ __align__(128) float g_h2  [ROWS];
__device__ __align__(128) float g_part[Bq * 8 * Hh];

__device__ __align__(128) __nv_bfloat16 g_cf_hl   [ROWS * Cc * 2];
__device__ __align__(128) __nv_bfloat16 g_x_hl    [ROWS * Hh * 2];
__device__ __align__(128) __nv_bfloat16 g_atto_hl [ROWS * Hh * 2];
__device__ __align__(128) __nv_bfloat16 g_att_hl  [ROWS * Hh * 2];
__device__ __align__(128) __nv_bfloat16 g_convT_hl[ROWS * Hh * 2];   // [8][512][1024]
__device__ __align__(128) __nv_bfloat16 g_adj_hl  [ROWS * Nn_ * 2];
__device__ __align__(128) __nv_bfloat16 g_wemb_hl [Hh * Cc * 2];
__device__ __align__(128) __nv_bfloat16 g_win_hl  [NLay * 3 * Hh * Hh * 2];
__device__ __align__(128) __nv_bfloat16 g_wout_hl [NLay * Hh * Hh * 2];
__device__ __align__(128) __nv_bfloat16 g_wconv_hl[NLay * Hh * Hh * 2];

// ---------------------------------------------------------------------------
// fp32 [R,K] row-major -> tiled hi/lo. grid(K/64, R/128), 256 threads.
// ---------------------------------------------------------------------------
__global__ __launch_bounds__(256)
void convert_hilo_kernel(const float* __restrict__ in,
                         __nv_bfloat16* __restrict__ out, int K)
{
    const size_t tileIdx = (size_t)blockIdx.y * gridDim.x + blockIdx.x;
    const float* src = in + (size_t)blockIdx.y * 128 * K + blockIdx.x * 64;
    char* dstT = (char*)out + (tileIdx << 15);
    for (int idx = threadIdx.x; idx < 8192; idx += 256) {
        const int r = idx >> 6, k = idx & 63;
        float v = src[(size_t)r * K + k];
        unsigned short hb, lb;
        split_bf16(v, hb, lb);
        const int off = swz(r, k);
        *(unsigned short*)(dstT + off)         = hb;
        *(unsigned short*)(dstT + 16384 + off) = lb;
    }
}

// ---------------------------------------------------------------------------
// HMMA GEMM (mma.sync bf16x3, fp32 accum). C tile 128x128, 256 threads,
// 8 warps of 32(M)x64(N). K chunks of 64, 3-stage cp.async pipeline.
// A tiled hi/lo, row tile = by. B tiled hi/lo, row tile = bx (B is [N,K]).
// MODE 0: fp32 out.  1: hi/lo tiled out.  2: hi/lo tiled TRANSPOSED (conv).
// MODE 3: fp32 + hi/lo tiled.
// Stage layout: Ahi(16K) Alo(16K) Bhi(16K) Blo(16K) = 64KB.
// ---------------------------------------------------------------------------
#define GEMM_SMEM (3 * 65536 + 1024)

template<int MODE>
__global__ __launch_bounds__(256)
void mmagemm(const __nv_bfloat16* __restrict__ Ahl,
             const __nv_bfloat16* __restrict__ Bhl,
             const float* __restrict__ bias,
             float* __restrict__ Cf,
             __nv_bfloat16* __restrict__ Ohl,
             int kChunks, int Ntot, int bTileBase, int bBatchStride)
{
    extern __shared__ __align__(1024) char smem[];
    const uint32_t sb = smem_u32(smem);
    const int tid  = threadIdx.x;
    const int bx   = blockIdx.x, by = blockIdx.y;
    const int wid  = tid >> 5, lane = tid & 31;
    const int m0   = (wid & 3) * 32;
    const int n0   = (wid >> 2) * 64;

    float* bias_sm = (float*)(smem + 3 * 65536);
    if (bias && tid < 128) bias_sm[tid] = bias[bx * 128 + tid];

    const size_t aBase = (size_t)by * kChunks;
    const size_t bBase = (size_t)bTileBase + (size_t)(by >> 3) * bBatchStride
                       + (size_t)bx * kChunks;

    auto load = [&](int c) {
        const uint32_t st = sb + (c % 3) * 65536;
        const char* gA = (const char*)Ahl + ((aBase + c) << 15);
        const char* gB = (const char*)Bhl + ((bBase + c) << 15);
#pragma unroll
        for (int i = 0; i < 8; i++) {
            const uint32_t off = (uint32_t)(tid + i * 256) * 16;
            CP_ASYNC_16(st + off,         gA + off);
            CP_ASYNC_16(st + 32768 + off, gB + off);
        }
        CP_COMMIT();
    };
    const int npre = kChunks < 3 ? kChunks : 3;
    for (int c = 0; c < npre; c++) load(c);

    float acc[2][8][4];
#pragma unroll
    for (int i = 0; i < 2; i++)
#pragma unroll
        for (int j = 0; j < 8; j++)
#pragma unroll
            for (int e = 0; e < 4; e++) acc[i][j][e] = 0.f;

    for (int c = 0; c < kChunks; c++) {
        const int rem = kChunks - 1 - c;
        if      (rem >= 2) asm volatile("cp.async.wait_group 2;" ::: "memory");
        else if (rem == 1) asm volatile("cp.async.wait_group 1;" ::: "memory");
        else               asm volatile("cp.async.wait_group 0;" ::: "memory");
        __syncthreads();

        const uint32_t st  = sb + (c % 3) * 65536;
        const uint32_t aHi = st, aLo = st + 16384;
        const uint32_t bHi = st + 32768, bLo = st + 49152;

#pragma unroll
        for (int ks = 0; ks < 4; ks++) {
            const int kk = ks * 16 + ((lane >> 4) << 3);
            const int rT = lane & 15;
            uint32_t ah[2][4], al[2][4], bh[4][4], bl[4][4];
#pragma unroll
            for (int mt = 0; mt < 2; mt++) {
                const int off = swz(m0 + mt * 16 + rT, kk);
                LDSM4(ah[mt], aHi + off);
                LDSM4(al[mt], aLo + off);
            }
#pragma unroll
            for (int bt = 0; bt < 4; bt++) {
                const int off = swz(n0 + bt * 16 + rT, kk);
                LDSM4(bh[bt], bHi + off);
                LDSM4(bl[bt], bLo + off);
            }
#pragma unroll
            for (int mt = 0; mt < 2; mt++)
#pragma unroll
                for (int nt = 0; nt < 8; nt++) {
                    const int bt = nt >> 1, pr = nt & 1;
                    MMA_BF16(acc[mt][nt], ah[mt], bh[bt][pr], bh[bt][pr + 2]);
                    MMA_BF16(acc[mt][nt], ah[mt], bl[bt][pr], bl[bt][pr + 2]);
                    MMA_BF16(acc[mt][nt], al[mt], bh[bt][pr], bh[bt][pr + 2]);
                }
        }
        __syncthreads();
        if (c + 3 < kChunks) load(c + 3);
    }

    // ---------------- epilogue ----------------
    const int rQ = lane >> 2;            // 0..7
    const int cQ = (lane & 3) * 2;       // 0,2,4,6

#pragma unroll
    for (int mt = 0; mt < 2; mt++) {
#pragma unroll
        for (int nt = 0; nt < 8; nt++) {
            const int cl = n0 + nt * 8 + cQ;            // local col (even)
            float v[4];
#pragma unroll
            for (int e = 0; e < 4; e++) v[e] = acc[mt][nt][e];
            if (bias) {
                v[0] += bias_sm[cl];     v[1] += bias_sm[cl + 1];
                v[2] += bias_sm[cl];     v[3] += bias_sm[cl + 1];
            }
            const int rl0 = m0 + mt * 16 + rQ;          // local rows rl0, rl0+8

            if (MODE == 0 || MODE == 3) {
                float* p0 = Cf + (size_t)(by * 128 + rl0) * Ntot + bx * 128 + cl;
                float* p1 = p0 + (size_t)8 * Ntot;
                *reinterpret_cast<float2*>(p0) = make_float2(v[0], v[1]);
                *reinterpret_cast<float2*>(p1) = make_float2(v[2], v[3]);
            }
            if (MODE == 1 || MODE == 3) {
                const size_t tile = (size_t)by * (Ntot >> 6) + bx * 2 + (cl >> 6);
                char* tb = (char*)Ohl + (tile << 15);
                const int k = cl & 63;
                unsigned short h0, l0, h1, l1;
#pragma unroll
                for (int half = 0; half < 2; half++) {
                    const int rr = rl0 + half * 8;
                    split_bf16(v[half * 2 + 0], h0, l0);
                    split_bf16(v[half * 2 + 1], h1, l1);
                    const int off = swz(rr, k);
                    *(uint32_t*)(tb + off)         = (uint32_t)h0 | ((uint32_t)h1 << 16);
                    *(uint32_t*)(tb + 16384 + off) = (uint32_t)l0 | ((uint32_t)l1 << 16);
                }
            }
            if (MODE == 2) {
                // transposed: output row' = local col, k' = global M row
#pragma unroll
                for (int half = 0; half < 2; half++) {
                    const int rr = rl0 + half * 8;      // local M row
                    const size_t tile = (size_t)(by >> 3) * 64 + (size_t)bx * 16
                                      + (by & 7) * 2 + (rr >> 6);
                    char* tb = (char*)Ohl + (tile << 15);
                    const int kf = rr & 63;
#pragma unroll
                    for (int e = 0; e < 2; e++) {
                        unsigned short hb, lb;
                        split_bf16(v[half * 2 + e], hb, lb);
                        const int off = swz(cl + e, kf);
                        *(unsigned short*)(tb + off)         = hb;
                        *(unsigned short*)(tb + 16384 + off) = lb;
                    }
                }
            }
        }
    }
}

// ---------------------------------------------------------------------------
// Attention over the B=8 axis; writes output directly as hi/lo tiles.
// ---------------------------------------------------------------------------
__global__ __launch_bounds__(64)
void attention_kernel(const float* __restrict__ qkv, __nv_bfloat16* __restrict__ ohl)
{
    const int nh = blockIdx.x;
    const int n  = nh >> 3;
    const int h  = nh & 7;
    const int t  = threadIdx.x;

    __shared__ float q[8][64];
    __shared__ float k[8][65];
    __shared__ float v[8][65];
    __shared__ float a[8][9];

    const int row3H = 3 * Hh;
    const float* base = qkv + (long long)n * row3H + h * DH;
#pragma unroll
    for (int i = 0; i < Bq; i++) {
        const float* p = base + (long long)i * Nn_ * row3H;
        q[i][t] = p[t];
        k[i][t] = p[Hh + t];
        v[i][t] = p[2 * Hh + t];
    }
    __syncthreads();

    {
        const int si = t >> 3, sj = t & 7;
        float s = 0.f;
#pragma unroll
        for (int d = 0; d < DH; d++) s += q[si][d] * k[sj][d];
        a[si][sj] = s * 0.125f;
    }
    __syncthreads();

    if (t < Bq) {
        float m = -1e30f;
#pragma unroll
        for (int j = 0; j < Bq; j++) m = fmaxf(m, a[t][j]);
        float sum = 0.f;
#pragma unroll
        for (int j = 0; j < Bq; j++) { float e = expf(a[t][j] - m); a[t][j] = e; sum += e; }
        float inv = 1.f / sum;
#pragma unroll
        for (int j = 0; j < Bq; j++) a[t][j] *= inv;
    }
    __syncthreads();

    const int r = n & 127;
    const int off = swz(r, t);
#pragma unroll
    for (int i = 0; i < Bq; i++) {
        float o = 0.f;
#pragma unroll
        for (int j = 0; j < Bq; j++) o += a[i][j] * v[j][t];
        const size_t tile = ((size_t)i * 8 + (n >> 7)) * 8 + h;
        char* tb = (char*)ohl + (tile << 15);
        unsigned short hb, lb;
        split_bf16(o, hb, lb);
        *(unsigned short*)(tb + off)         = hb;
        *(unsigned short*)(tb + 16384 + off) = lb;
    }
}

// ---------------------------------------------------------------------------
// out = layernorm(x + agg); also emits hi/lo tiles when ohl != nullptr.
// ---------------------------------------------------------------------------
__global__ __launch_bounds__(256)
void add_ln_kernel(const float* __restrict__ x, const float* __restrict__ agg,
                   float* __restrict__ out, __nv_bfloat16* __restrict__ ohl)
{
    const int row = blockIdx.x;
    const int t   = threadIdx.x;
    const float* xr = x   + (long long)row * Hh;
    const float* ar = agg + (long long)row * Hh;

    float v0 = xr[t]       + ar[t];
    float v1 = xr[t + 256] + ar[t + 256];
    float s  = v0 + v1;
    float ss = v0 * v0 + v1 * v1;

#pragma unroll
    for (int o = 16; o; o >>= 1) {
        s  += __shfl_xor_sync(0xffffffffu, s,  o);
        ss += __shfl_xor_sync(0xffffffffu, ss, o);
    }
    __shared__ float sbm[8], qbm[8];
    if ((t & 31) == 0) { sbm[t >> 5] = s; qbm[t >> 5] = ss; }
    __syncthreads();
    if (t < 32) {
        float a2 = (t < 8) ? sbm[t] : 0.f;
        float b2 = (t < 8) ? qbm[t] : 0.f;
#pragma unroll
        for (int o = 4; o; o >>= 1) {
            a2 += __shfl_xor_sync(0xffffffffu, a2, o);
            b2 += __shfl_xor_sync(0xffffffffu, b2, o);
        }
        if (t == 0) { sbm[0] = a2; qbm[0] = b2; }
    }
    __syncthreads();

    const float mean = sbm[0] * (1.f / Hh);
    const float var  = qbm[0] * (1.f / Hh) - mean * mean;
    const float inv  = rsqrtf(var + 1e-5f);
    const float o0 = (v0 - mean) * inv;
    const float o1 = (v1 - mean) * inv;
    float* orow = out + (long long)row * Hh;
    orow[t]       = o0;
    orow[t + 256] = o1;

    if (ohl) {
        const int r = row & 127;
        const size_t rt8 = (size_t)(row >> 7) * 8;
#pragma unroll
        for (int e = 0; e < 2; e++) {
            const int c = t + e * 256;
            const float vv = e ? o1 : o0;
            char* tb = (char*)ohl + ((rt8 + (c >> 6)) << 15);
            const int off = swz(r, c & 63);
            unsigned short hb, lb;
            split_bf16(vv, hb, lb);
            *(unsigned short*)(tb + off)         = hb;
            *(unsigned short*)(tb + 16384 + off) = lb;
        }
    }
}

// ---------------------------------------------------------------------------
// Heads: mastery, diff[5], h1, h2 in one pass over x rows.
// ---------------------------------------------------------------------------
__global__ __launch_bounds__(256)
void heads_kernel(const float* __restrict__ x,
                  const float* __restrict__ Wcls, const float* __restrict__ bcls,
                  const float* __restrict__ Wdiff, const float* __restrict__ bdiff,
                  const float* __restrict__ Wpre,
                  float* __restrict__ mastery, float* __restrict__ diff,
                  float* __restrict__ h1, float* __restrict__ h2)
{
    const int row = blockIdx.x;
    const int t   = threadIdx.x;
    const float* xr = x + (long long)row * Hh;

    float acc[8] = {0.f, 0.f, 0.f, 0.f, 0.f, 0.f, 0.f, 0.f};
    for (int c = t; c < Hh; c += 256) {
        const float xv = xr[c];
        acc[0] += xv * Wcls[c];
#pragma unroll
        for (int kk = 0; kk < 5; kk++) acc[1 + kk] += xv * Wdiff[kk * Hh + c];
        acc[6] += xv * Wpre[c];
        acc[7] += xv * Wpre[Hh + c];
    }

    __shared__ float rsm[8][8];
#pragma unroll
    for (int kk = 0; kk < 8; kk++) {
        float v = acc[kk];
#pragma unroll
        for (int o = 16; o; o >>= 1) v += __shfl_xor_sync(0xffffffffu, v, o);
        if ((t & 31) == 0) rsm[kk][t >> 5] = v;
    }
    __syncthreads();
    if (t < 8) {
        float s = 0.f;
#pragma unroll
        for (int w = 0; w < 8; w++) s += rsm[t][w];
        if      (t == 0) mastery[row] = s + bcls[0];
        else if (t < 6)  diff[(long long)row * 5 + (t - 1)] = s + bdiff[t - 1];
        else if (t == 6) h1[row] = s;
        else             h2[row] = s;
    }
}

__global__ __launch_bounds__(256)
void prereq_kernel(const float* __restrict__ h1, const float* __restrict__ h2,
                   const float* __restrict__ bpre, float* __restrict__ out)
{
    const long long idx = (long long)blockIdx.x * blockDim.x + threadIdx.x;
    const int j = (int)(idx & (Nn_ - 1));
    const int i = (int)((idx >> 10) & (Nn_ - 1));
    const int b = (int)(idx >> 20);
    if (b >= Bq || i == j) return;
    const long long o = (long long)b * Nn_ * (Nn_ - 1) + (long long)i * (Nn_ - 1) + j - (j > i);
    out[o] = h1[b * Nn_ + i] + h2[b * Nn_ + j] + bpre[0];
}

__global__ __launch_bounds__(512)
void pool_partial_kernel(const float* __restrict__ x, float* __restrict__ part)
{
    const int b = blockIdx.x, g = blockIdx.y, t = threadIdx.x;
    float s = 0.f;
    const float* base = x + ((long long)b * Nn_ + g * 128) * Hh + t;
    for (int n = 0; n < 128; n++) s += base[(long long)n * Hh];
    part[((long long)b * 8 + g) * Hh + t] = s;
}

__global__ __launch_bounds__(512)
void graph_kernel(const float* __restrict__ part, const float* __restrict__ Wp,
                  const float* __restrict__ bp, float* __restrict__ out)
{
    const int b = blockIdx.x, t = threadIdx.x;
    __shared__ float xm[Hh];
    float s = 0.f;
#pragma unroll
    for (int g = 0; g < 8; g++) s += part[((long long)b * 8 + g) * Hh + t];
    xm[t] = s * (1.f / Nn_);
    __syncthreads();
    float acc = 0.f;
    const float* wr = Wp + (long long)t * Hh;
    for (int c = 0; c < Hh; c++) acc += xm[c] * wr[c];
    out[(long long)b * Hh + t] = acc + bp[t];
}

// ---------------------------------------------------------------------------
// Launcher
// ---------------------------------------------------------------------------
extern "C" void kernel_launch(void* const* d_in, const int* in_sizes, int n_in,
                              void* d_out, int out_size)
{
    (void)in_sizes; (void)n_in; (void)out_size;
    const float* CF    = (const float*)d_in[0];
    const float* ADJ   = (const float*)d_in[1];
    const float* Wemb  = (const float*)d_in[4];
    const float* bemb  = (const float*)d_in[5];
    const float* Win   = (const float*)d_in[6];
    const float* bin   = (const float*)d_in[7];
    const float* Wout  = (const float*)d_in[8];
    const float* bout  = (const float*)d_in[9];
    const float* Wconv = (const float*)d_in[10];
    const float* bconv = (const float*)d_in[11];
    const float* Wcls  = (const float*)d_in[12];
    const float* bcls  = (const float*)d_in[13];
    const float* Wdiff = (const float*)d_in[14];
    const float* bdiff = (const float*)d_in[15];
    const float* Wpre  = (const float*)d_in[16];
    const float* bpre  = (const float*)d_in[17];
    const float* Wpool = (const float*)d_in[18];
    const float* bpool = (const float*)d_in[19];

    float *x, *qkv, *agg, *h1, *h2, *part;
    __nv_bfloat16 *cf_hl, *x_hl, *atto_hl, *att_hl, *convT_hl, *adj_hl;
    __nv_bfloat16 *wemb_hl, *win_hl, *wout_hl, *wconv_hl;
    cudaGetSymbolAddress((void**)&x,        g_x);
    cudaGetSymbolAddress((void**)&qkv,      g_qkv);
    cudaGetSymbolAddress((void**)&agg,      g_agg);
    cudaGetSymbolAddress((void**)&h1,       g_h1);
    cudaGetSymbolAddress((void**)&h2,       g_h2);
    cudaGetSymbolAddress((void**)&part,     g_part);
    cudaGetSymbolAddress((void**)&cf_hl,    g_cf_hl);
    cudaGetSymbolAddress((void**)&x_hl,     g_x_hl);
    cudaGetSymbolAddress((void**)&atto_hl,  g_atto_hl);
    cudaGetSymbolAddress((void**)&att_hl,   g_att_hl);
    cudaGetSymbolAddress((void**)&convT_hl, g_convT_hl);
    cudaGetSymbolAddress((void**)&adj_hl,   g_adj_hl);
    cudaGetSymbolAddress((void**)&wemb_hl,  g_wemb_hl);
    cudaGetSymbolAddress((void**)&win_hl,   g_win_hl);
    cudaGetSymbolAddress((void**)&wout_hl,  g_wout_hl);
    cudaGetSymbolAddress((void**)&wconv_hl, g_wconv_hl);

    cudaFuncSetAttribute(mmagemm<0>, cudaFuncAttributeMaxDynamicSharedMemorySize, GEMM_SMEM);
    cudaFuncSetAttribute(mmagemm<1>, cudaFuncAttributeMaxDynamicSharedMemorySize, GEMM_SMEM);
    cudaFuncSetAttribute(mmagemm<2>, cudaFuncAttributeMaxDynamicSharedMemorySize, GEMM_SMEM);
    cudaFuncSetAttribute(mmagemm<3>, cudaFuncAttributeMaxDynamicSharedMemorySize, GEMM_SMEM);

    float* out   = (float*)d_out;
    float* out_x = out + OFF_X;
    float* out_m = out + OFF_M;
    float* out_d = out + OFF_D;
    float* out_p = out + OFF_P;
    float* out_g = out + OFF_G;

    // --- operand conversion to tiled hi/lo bf16 ---
    convert_hilo_kernel<<<dim3(Cc / 64, ROWS / 128), 256>>>(CF,    cf_hl,    Cc);
    convert_hilo_kernel<<<dim3(Cc / 64, Hh / 128),   256>>>(Wemb,  wemb_hl,  Cc);
    convert_hilo_kernel<<<dim3(Hh / 64, (NLay * 3 * Hh) / 128), 256>>>(Win,   win_hl,   Hh);
    convert_hilo_kernel<<<dim3(Hh / 64, (NLay * Hh) / 128),     256>>>(Wout,  wout_hl,  Hh);
    convert_hilo_kernel<<<dim3(Hh / 64, (NLay * Hh) / 128),     256>>>(Wconv, wconv_hl, Hh);
    convert_hilo_kernel<<<dim3(Nn_ / 64, ROWS / 128),           256>>>(ADJ,   adj_hl,   Nn_);

    // emb: x = CF @ Wemb^T + b  (fp32 + hi/lo)
    mmagemm<3><<<dim3(4, 64), 256, GEMM_SMEM>>>(cf_hl, wemb_hl, bemb, x, x_hl,
                                                Cc / 64, Hh, 0, 0);

    for (int l = 0; l < NLay; l++) {
        const bool lastL = (l == NLay - 1);
        // qkv = x @ W_in^T + b (fp32)
        mmagemm<0><<<dim3(12, 64), 256, GEMM_SMEM>>>(x_hl, win_hl, bin + l * 3 * Hh,
                                                     qkv, nullptr, Hh / 64, 3 * Hh,
                                                     l * (3 * Hh / 128) * (Hh / 64), 0);
        // attention -> atto (hi/lo tiles)
        attention_kernel<<<Nn_ * NHd, 64>>>(qkv, atto_hl);
        // att = atto @ W_out^T + b (hi/lo tiles)
        mmagemm<1><<<dim3(4, 64), 256, GEMM_SMEM>>>(atto_hl, wout_hl, bout + l * Hh,
                                                    nullptr, att_hl, Hh / 64, Hh,
                                                    l * (Hh / 128) * (Hh / 64), 0);
        // convT = (att @ W_conv^T + b)^T per batch (hi/lo tiles)
        mmagemm<2><<<dim3(4, 64), 256, GEMM_SMEM>>>(att_hl, wconv_hl, bconv + l * Hh,
                                                    nullptr, convT_hl, Hh / 64, Hh,
                                                    l * (Hh / 128) * (Hh / 64), 0);
        // agg[b] = adj[b] @ conv[b]  (batched; B batch stride = 4*16 tiles)
        mmagemm<0><<<dim3(4, 64), 256, GEMM_SMEM>>>(adj_hl, convT_hl, nullptr,
                                                    agg, nullptr, Nn_ / 64, Hh,
                                                    0, (Hh / 128) * (Nn_ / 64));
        // x = LN(x + agg), emit hi/lo for next layer (skip hl on last)
        add_ln_kernel<<<ROWS, 256>>>(x, agg, lastL ? out_x : x,
                                     lastL ? nullptr : x_hl);
    }

    heads_kernel<<<ROWS, 256>>>(out_x, Wcls, bcls, Wdiff, bdiff, Wpre,
                                out_m, out_d, h1, h2);
    prereq_kernel<<<(Bq * Nn_ * Nn_) / 256, 256>>>(h1, h2, bpre, out_p);
    pool_partial_kernel<<<dim3(Bq, 8), 512>>>(out_x, part);
    graph_kernel<<<Bq, 512>>>(part, Wpool, bpool, out_g);
}